// round 8
// baseline (speedup 1.0000x reference)
#include <cuda_runtime.h>
#include <cstdint>
#include <math.h>

#define NB 2
#define SS 2048
#define DD 768
#define EE 8
#define HH 2048
#define NHH 8
#define NTOK (NB*SS)

// ---------------- scratch ----------------
__device__ float g_q[NTOK*DD];
__device__ float g_k[NTOK*DD];
__device__ float g_v[NTOK*DD];
__device__ float g_o[NTOK*DD];
__device__ float g_cap[NTOK*DD];
__device__ float g_Hg[(size_t)EE*NTOK*HH];
__device__ float g_zsum[NTOK*DD];
__device__ float g_caplog[NTOK*EE];
__device__ float g_aclog[NTOK*EE];
__device__ float g_pc[NTOK*EE];
__device__ float g_pa[NTOK*EE];
__device__ float g_masks[NTOK*2];
__device__ float g_hilog[4];
__device__ float g_accum[17];

// ---------------- threefry2x32 (JAX partitionable) ----------------
__host__ __device__ __forceinline__ uint32_t rotl32(uint32_t v,int r){return (v<<r)|(v>>(32-r));}
__host__ __device__ __forceinline__ void threefry_full(uint32_t k0,uint32_t k1,uint32_t x0,uint32_t x1,
                                                       uint32_t* o0,uint32_t* o1){
  uint32_t ks2 = k0 ^ k1 ^ 0x1BD11BDAu;
  x0 += k0; x1 += k1;
#define TFR(r) x0 += x1; x1 = rotl32(x1,(r)); x1 ^= x0;
  TFR(13) TFR(15) TFR(26) TFR(6)  x0+=k1;  x1+=ks2+1u;
  TFR(17) TFR(29) TFR(16) TFR(24) x0+=ks2; x1+=k0+2u;
  TFR(13) TFR(15) TFR(26) TFR(6)  x0+=k0;  x1+=k1+3u;
  TFR(17) TFR(29) TFR(16) TFR(24) x0+=k1;  x1+=ks2+4u;
  TFR(13) TFR(15) TFR(26) TFR(6)  x0+=ks2; x1+=k0+5u;
#undef TFR
  *o0 = x0; *o1 = x1;
}
__device__ __forceinline__ float gumbel_at(uint32_t k0,uint32_t k1,uint32_t idx){
  uint32_t o0,o1;
  threefry_full(k0,k1,0u,idx,&o0,&o1);
  uint32_t bits = o0 ^ o1;
  float u = __uint_as_float(0x3f800000u | (bits>>9)) - 1.0f;
  u = fmaxf(u, 1.17549435e-38f);
  return -logf(-logf(u));
}

__global__ void zero_k(float* p, long long n){
  long long i=(long long)blockIdx.x*blockDim.x+threadIdx.x, st=(long long)gridDim.x*blockDim.x;
  for(; i<n; i+=st) p[i]=0.f;
}

// ---------------- TF32 helpers ----------------
__device__ __forceinline__ float to_tf32(float f){
  uint32_t o;
  asm("cvt.rna.tf32.f32 %0, %1;" : "=r"(o) : "f"(f));
  return __uint_as_float(o);
}
__device__ __forceinline__ void mma_tf32(float* c, const uint32_t* a, const uint32_t* b){
  asm volatile("mma.sync.aligned.m16n8k8.row.col.f32.tf32.tf32.f32 "
    "{%0,%1,%2,%3},{%4,%5,%6,%7},{%8,%9},{%0,%1,%2,%3};"
    : "+f"(c[0]),"+f"(c[1]),"+f"(c[2]),"+f"(c[3])
    : "r"(a[0]),"r"(a[1]),"r"(a[2]),"r"(a[3]),"r"(b[0]),"r"(b[1]));
}

// ------------- 3xTF32 tensor GEMM: C[M,N] = A[M,K] @ W[N,K]^T ---------------
// CTA 128x128, 512 threads (16 warps, 4x4), warp tile 32x32.
// Split: x = hi + lo (both tf32); acc += lo*hi + hi*lo + hi*hi -> ~fp32 accuracy.
// K multiple of 32, M multiple of 128, N-edge guarded.
// EPI 0: C=acc+bias[col]  EPI 1: C=silu(Dm)*acc  EPI 2: atomicAdd(C, probs*mask*acc)
#define TGS (32*136)
#define TG_SMEM (4*TGS*4)
template<int EPI>
__global__ __launch_bounds__(512)
void tgemm_k(int M,int N,int K,
             const float* __restrict__ A, long long lda, long long estrA,
             const float* __restrict__ W, long long ldw, long long estrW,
             float* __restrict__ C, long long ldc, long long estrC,
             const float* __restrict__ bias,
             const float* __restrict__ Dm, long long ldd, long long estrD,
             const float* __restrict__ probs, const float* __restrict__ maskp)
{
  const int e = blockIdx.z;
  A += (long long)e*estrA;  W += (long long)e*estrW;  C += (long long)e*estrC;
  if(EPI==1) Dm += (long long)e*estrD;

  extern __shared__ float smp[];
  float* Ah = smp;            // [32][136]
  float* Al = smp + TGS;
  float* Wh = smp + 2*TGS;
  float* Wl = smp + 3*TGS;

  const int m0 = blockIdx.y*128, n0 = blockIdx.x*128;
  const int tid = threadIdx.x, w = tid>>5, lane = tid&31;
  const int g = lane>>2, tig = lane&3;
  const int wm = (w>>2)*32, wn = (w&3)*32;

  // loader mapping: column group cg (4 k's), two rows per thread
  const int cg = w>>1;                       // 0..7
  const int lrow = ((w&1)<<6) + lane;        // 0..127 two halves; +32*i

  float acc[2][4][4];
#pragma unroll
  for(int mf=0;mf<2;mf++)
#pragma unroll
    for(int nf=0;nf<4;nf++)
#pragma unroll
      for(int c=0;c<4;c++) acc[mf][nf][c]=0.f;

  const int nchunks = K>>5;
  float4 pa[2], pw[2];

  // prologue loads (chunk 0)
#pragma unroll
  for(int i=0;i<2;i++){
    const int row = lrow + 32*i;
    pa[i] = *(const float4*)(A + (long long)(m0+row)*lda + cg*4);
    pw[i] = (n0+row < N) ? *(const float4*)(W + (long long)(n0+row)*ldw + cg*4)
                         : make_float4(0.f,0.f,0.f,0.f);
  }

  for(int c=0;c<nchunks;c++){
    // split + store to smem
#pragma unroll
    for(int i=0;i<2;i++){
      const int row = lrow + 32*i;
      float av[4] = {pa[i].x,pa[i].y,pa[i].z,pa[i].w};
      float wv[4] = {pw[i].x,pw[i].y,pw[i].z,pw[i].w};
#pragma unroll
      for(int j=0;j<4;j++){
        float ahi = to_tf32(av[j]);
        Ah[(cg*4+j)*136 + row] = ahi;
        Al[(cg*4+j)*136 + row] = to_tf32(av[j]-ahi);
        float whi = to_tf32(wv[j]);
        Wh[(cg*4+j)*136 + row] = whi;
        Wl[(cg*4+j)*136 + row] = to_tf32(wv[j]-whi);
      }
    }
    __syncthreads();

    // prefetch next chunk
    if(c+1 < nchunks){
      const long long kc = (long long)(c+1)*32 + cg*4;
#pragma unroll
      for(int i=0;i<2;i++){
        const int row = lrow + 32*i;
        pa[i] = *(const float4*)(A + (long long)(m0+row)*lda + kc);
        pw[i] = (n0+row < N) ? *(const float4*)(W + (long long)(n0+row)*ldw + kc)
                             : make_float4(0.f,0.f,0.f,0.f);
      }
    }

#pragma unroll
    for(int ks=0;ks<4;ks++){
      const int kb = ks*8;
      uint32_t ah[2][4], al[2][4];
#pragma unroll
      for(int mf=0;mf<2;mf++){
        const int m = wm + mf*16 + g;
        ah[mf][0]=__float_as_uint(Ah[(kb+tig  )*136+m  ]);
        ah[mf][1]=__float_as_uint(Ah[(kb+tig  )*136+m+8]);
        ah[mf][2]=__float_as_uint(Ah[(kb+tig+4)*136+m  ]);
        ah[mf][3]=__float_as_uint(Ah[(kb+tig+4)*136+m+8]);
        al[mf][0]=__float_as_uint(Al[(kb+tig  )*136+m  ]);
        al[mf][1]=__float_as_uint(Al[(kb+tig  )*136+m+8]);
        al[mf][2]=__float_as_uint(Al[(kb+tig+4)*136+m  ]);
        al[mf][3]=__float_as_uint(Al[(kb+tig+4)*136+m+8]);
      }
      uint32_t bh[4][2], bl[4][2];
#pragma unroll
      for(int nf=0;nf<4;nf++){
        const int n = wn + nf*8 + g;
        bh[nf][0]=__float_as_uint(Wh[(kb+tig  )*136+n]);
        bh[nf][1]=__float_as_uint(Wh[(kb+tig+4)*136+n]);
        bl[nf][0]=__float_as_uint(Wl[(kb+tig  )*136+n]);
        bl[nf][1]=__float_as_uint(Wl[(kb+tig+4)*136+n]);
      }
#pragma unroll
      for(int mf=0;mf<2;mf++)
#pragma unroll
        for(int nf=0;nf<4;nf++){
          mma_tf32(acc[mf][nf], al[mf], bh[nf]);
          mma_tf32(acc[mf][nf], ah[mf], bl[nf]);
          mma_tf32(acc[mf][nf], ah[mf], bh[nf]);
        }
    }
    __syncthreads();
  }

  // epilogue
#pragma unroll
  for(int mf=0;mf<2;mf++){
    const int row0 = m0 + wm + mf*16 + g;
    const int row1 = row0 + 8;
    float rs0=0.f, rs1=0.f;
    if(EPI==2){
      rs0 = probs[(long long)row0*8+e]*maskp[(long long)row0*2];
      rs1 = probs[(long long)row1*8+e]*maskp[(long long)row1*2];
    }
#pragma unroll
    for(int nf=0;nf<4;nf++){
      const int col0 = n0 + wn + nf*8 + 2*tig;
#pragma unroll
      for(int cc=0;cc<2;cc++){
        const int col = col0 + cc;
        if(col < N){
          const long long ci0 = (long long)row0*ldc + col;
          const long long ci1 = (long long)row1*ldc + col;
          const float v0 = acc[mf][nf][cc], v1 = acc[mf][nf][2+cc];
          if(EPI==0){
            const float bb = bias ? bias[col] : 0.f;
            C[ci0] = v0 + bb;  C[ci1] = v1 + bb;
          } else if(EPI==1){
            float h0 = Dm[(long long)row0*ldd+col];
            float h1 = Dm[(long long)row1*ldd+col];
            C[ci0] = (h0/(1.f+expf(-h0)))*v0;
            C[ci1] = (h1/(1.f+expf(-h1)))*v1;
          } else {
            atomicAdd(&C[ci0], rs0*v0);
            atomicAdd(&C[ci1], rs1*v1);
          }
        }
      }
    }
  }
}

// ---------------- flash attention (64x64 tiles, online softmax, fp32) ----------------
#define ATT_SMEM ((3*64*97 + 64*65)*4)
__global__ __launch_bounds__(256)
void attn_k(const float* __restrict__ Q, const float* __restrict__ Kg,
            const float* __restrict__ Vg, float* __restrict__ O)
{
  extern __shared__ float sm[];
  float* Qs = sm;
  float* Ks = sm + 64*97;
  float* Vs = sm + 2*64*97;
  float* Ps = sm + 3*64*97;
  const int qt=blockIdx.x, h=blockIdx.y, b=blockIdx.z;
  const int tid=threadIdx.x, ty=tid>>4, tx=tid&15;
  const long long rowbase=(long long)b*SS;

  for(int idx=tid; idx<64*96; idx+=256){
    int r=idx/96, d=idx-r*96;
    Qs[r*97+d] = Q[(rowbase+qt*64+r)*DD + h*96 + d];
  }
  float m[4], l[4], accv[4][6];
#pragma unroll
  for(int i=0;i<4;i++){ m[i]=-1e30f; l[i]=0.f;
#pragma unroll
    for(int d2=0;d2<6;d2++) accv[i][d2]=0.f; }
  const float scale = 1.0f/sqrtf(96.0f);

  for(int t=0;t<SS/64;t++){
    __syncthreads();
    for(int idx=tid; idx<64*96; idx+=256){
      int r=idx/96, d=idx-r*96;
      long long gg=(rowbase+t*64+r)*DD + h*96 + d;
      Ks[r*97+d]=Kg[gg]; Vs[r*97+d]=Vg[gg];
    }
    __syncthreads();

    float s[4][4];
#pragma unroll
    for(int i=0;i<4;i++)
#pragma unroll
      for(int j=0;j<4;j++) s[i][j]=0.f;
    for(int d=0; d<96; d++){
      float a0=Qs[(4*ty+0)*97+d],a1=Qs[(4*ty+1)*97+d],a2=Qs[(4*ty+2)*97+d],a3=Qs[(4*ty+3)*97+d];
      float b0=Ks[(4*tx+0)*97+d],b1=Ks[(4*tx+1)*97+d],b2=Ks[(4*tx+2)*97+d],b3=Ks[(4*tx+3)*97+d];
      s[0][0]+=a0*b0; s[0][1]+=a0*b1; s[0][2]+=a0*b2; s[0][3]+=a0*b3;
      s[1][0]+=a1*b0; s[1][1]+=a1*b1; s[1][2]+=a1*b2; s[1][3]+=a1*b3;
      s[2][0]+=a2*b0; s[2][1]+=a2*b1; s[2][2]+=a2*b2; s[2][3]+=a2*b3;
      s[3][0]+=a3*b0; s[3][1]+=a3*b1; s[3][2]+=a3*b2; s[3][3]+=a3*b3;
    }
#pragma unroll
    for(int i=0;i<4;i++){
      float v0=s[i][0]*scale,v1=s[i][1]*scale,v2=s[i][2]*scale,v3=s[i][3]*scale;
      float mx=fmaxf(fmaxf(v0,v1),fmaxf(v2,v3));
#pragma unroll
      for(int off=8;off>=1;off>>=1) mx=fmaxf(mx,__shfl_xor_sync(0xffffffffu,mx,off));
      float mn=fmaxf(m[i],mx), al=expf(m[i]-mn);
      float p0=expf(v0-mn),p1=expf(v1-mn),p2=expf(v2-mn),p3=expf(v3-mn);
      Ps[(4*ty+i)*65+4*tx+0]=p0; Ps[(4*ty+i)*65+4*tx+1]=p1;
      Ps[(4*ty+i)*65+4*tx+2]=p2; Ps[(4*ty+i)*65+4*tx+3]=p3;
      float ps=p0+p1+p2+p3;
#pragma unroll
      for(int off=8;off>=1;off>>=1) ps+=__shfl_xor_sync(0xffffffffu,ps,off);
      l[i]=l[i]*al+ps; m[i]=mn;
#pragma unroll
      for(int d2=0;d2<6;d2++) accv[i][d2]*=al;
    }
    __syncthreads();
    for(int n=0;n<64;n++){
      float vv[6];
#pragma unroll
      for(int d2=0;d2<6;d2++) vv[d2]=Vs[n*97 + tx*6 + d2];
#pragma unroll
      for(int i=0;i<4;i++){
        float p=Ps[(4*ty+i)*65+n];
#pragma unroll
        for(int d2=0;d2<6;d2++) accv[i][d2]+=p*vv[d2];
      }
    }
  }
#pragma unroll
  for(int i=0;i<4;i++){
    float inv=1.f/l[i];
#pragma unroll
    for(int d2=0;d2<6;d2++)
      O[(rowbase+qt*64+4*ty+i)*DD + h*96 + tx*6+d2] = accv[i][d2]*inv;
  }
}

// ---------------- small kernels ----------------
__global__ void hilog_k(const float* t,const float* Whi,const float* bhi,float* hl){
  int w=threadIdx.x>>5, lane=threadIdx.x&31;
  if(w<4){
    int b=w>>1, j=w&1;
    float s=0.f;
    for(int kk=lane;kk<DD;kk+=32) s += t[b*DD+kk]*Whi[j*DD+kk];
#pragma unroll
    for(int off=16;off>=1;off>>=1) s+=__shfl_xor_sync(0xffffffffu,s,off);
    if(lane==0) hl[b*2+j]=s+bhi[j];
  }
}
__global__ void mask_k(const float* hl,float* mk,uint32_t k0,uint32_t k1){
  int n=blockIdx.x*blockDim.x+threadIdx.x;
  if(n>=NTOK) return;
  int b=n>>11;
  float a0=hl[b*2+0]+gumbel_at(k0,k1,(uint32_t)(2*n));
  float a1=hl[b*2+1]+gumbel_at(k0,k1,(uint32_t)(2*n+1));
  float mx=fmaxf(a0,a1);
  float e0=expf(a0-mx), e1=expf(a1-mx), inv=1.f/(e0+e1);
  mk[2*n+0]=e0*inv; mk[2*n+1]=e1*inv;
}
__global__ __launch_bounds__(256) void gate_k(const float* __restrict__ X,
                                              const float* __restrict__ Wg,
                                              const float* __restrict__ bg,
                                              float* __restrict__ outp){
  int gw=(blockIdx.x*256+threadIdx.x)>>5, lane=threadIdx.x&31;
  if(gw>=NTOK) return;
  const float* xr = X + (long long)gw*DD;
  float acc[8]={0,0,0,0,0,0,0,0};
  for(int kk=lane;kk<DD;kk+=32){
    float xv=xr[kk];
#pragma unroll
    for(int j=0;j<8;j++) acc[j]+=xv*Wg[j*DD+kk];
  }
#pragma unroll
  for(int j=0;j<8;j++){
    float s=acc[j];
#pragma unroll
    for(int off=16;off>=1;off>>=1) s+=__shfl_xor_sync(0xffffffffu,s,off);
    if(lane==0) outp[(long long)gw*8+j]=s+bg[j];
  }
}
__global__ void probs_k(const float* logit,float* pr,uint32_t k0,uint32_t k1){
  int n=blockIdx.x*blockDim.x+threadIdx.x;
  if(n>=NTOK) return;
  float a[8]; float mx=-1e30f;
#pragma unroll
  for(int j=0;j<8;j++){
    a[j]=(logit[n*8+j]+gumbel_at(k0,k1,(uint32_t)(n*8+j)))*0.5f;
    mx=fmaxf(mx,a[j]);
  }
  float sum=0.f;
#pragma unroll
  for(int j=0;j<8;j++){ a[j]=expf(a[j]-mx); sum+=a[j]; }
  float inv=1.f/sum;
#pragma unroll
  for(int j=0;j<8;j++) pr[n*8+j]=a[j]*inv;
}
__global__ void lossacc_k(const float* pc,const float* pa,const float* mk,float* acm){
  __shared__ float sh[17];
  if(threadIdx.x<17) sh[threadIdx.x]=0.f;
  __syncthreads();
  int n=blockIdx.x*blockDim.x+threadIdx.x;
  if(n<NTOK){
    float m0=mk[2*n], m1=mk[2*n+1];
#pragma unroll
    for(int j=0;j<8;j++) atomicAdd(&sh[j],   pc[n*8+j]*m0);
#pragma unroll
    for(int j=0;j<8;j++) atomicAdd(&sh[8+j], pa[n*8+j]*m1);
    atomicAdd(&sh[16], 8.f*(m0+m1));
  }
  __syncthreads();
  if(threadIdx.x<17) atomicAdd(&acm[threadIdx.x], sh[threadIdx.x]);
}
__global__ void lossfin_k(const float* acm,float* outp){
  if(threadIdx.x==0){
    float den=acm[16]+1e-10f, s=0.f;
    for(int j=0;j<16;j++){ float u=acm[j]/den; s += u*logf(u+1e-10f); }
    *outp = s/16.f;
  }
}

// ---------------- launcher ----------------
extern "C" void kernel_launch(void* const* d_in, const int* in_sizes, int n_in,
                              void* d_out, int out_size){
  const float* x        =(const float*)d_in[0];
  const float* time_    =(const float*)d_in[1];
  const float* caption  =(const float*)d_in[2];
  const float* acoustic =(const float*)d_in[3];
  const float* Wqkv     =(const float*)d_in[4];
  const float* bqkv     =(const float*)d_in[5];
  const float* Wo       =(const float*)d_in[6];
  const float* bo       =(const float*)d_in[7];
  const float* Whi      =(const float*)d_in[8];
  const float* bhi      =(const float*)d_in[9];
  const float* Wcg      =(const float*)d_in[10];
  const float* bcg      =(const float*)d_in[11];
  const float* Wag      =(const float*)d_in[12];
  const float* bag      =(const float*)d_in[13];
  const float* cw1      =(const float*)d_in[14];
  const float* cw2      =(const float*)d_in[15];
  const float* cw3      =(const float*)d_in[16];
  const float* aw1      =(const float*)d_in[17];
  const float* aw2      =(const float*)d_in[18];
  const float* aw3      =(const float*)d_in[19];
  const float* fw1      =(const float*)d_in[20];
  const float* fw2      =(const float*)d_in[21];
  const float* fw3      =(const float*)d_in[22];
  float* out=(float*)d_out;

  uint32_t sk[3][2];
  for(uint32_t j=0;j<3;j++) threefry_full(0u,42u,0u,j,&sk[j][0],&sk[j][1]);

  float *q,*k,*v,*o,*cap,*Hg,*zs,*clg,*alg,*pc,*pa,*mk,*hl,*ac;
  cudaGetSymbolAddress((void**)&q,g_q);     cudaGetSymbolAddress((void**)&k,g_k);
  cudaGetSymbolAddress((void**)&v,g_v);     cudaGetSymbolAddress((void**)&o,g_o);
  cudaGetSymbolAddress((void**)&cap,g_cap); cudaGetSymbolAddress((void**)&Hg,g_Hg);
  cudaGetSymbolAddress((void**)&zs,g_zsum); cudaGetSymbolAddress((void**)&clg,g_caplog);
  cudaGetSymbolAddress((void**)&alg,g_aclog);cudaGetSymbolAddress((void**)&pc,g_pc);
  cudaGetSymbolAddress((void**)&pa,g_pa);   cudaGetSymbolAddress((void**)&mk,g_masks);
  cudaGetSymbolAddress((void**)&hl,g_hilog);cudaGetSymbolAddress((void**)&ac,g_accum);

  cudaFuncSetAttribute(attn_k, cudaFuncAttributeMaxDynamicSharedMemorySize, ATT_SMEM);
  cudaFuncSetAttribute(tgemm_k<0>, cudaFuncAttributeMaxDynamicSharedMemorySize, TG_SMEM);
  cudaFuncSetAttribute(tgemm_k<1>, cudaFuncAttributeMaxDynamicSharedMemorySize, TG_SMEM);
  cudaFuncSetAttribute(tgemm_k<2>, cudaFuncAttributeMaxDynamicSharedMemorySize, TG_SMEM);

  zero_k<<<256,256>>>(zs,(long long)NTOK*DD);
  zero_k<<<1,32>>>(ac,17);

  dim3 g768(6,32,1), gE2048(16,32,8), gE768(6,32,8), gF2048(16,32,8), gF96(1,32,8);
  const long long HgE=(long long)NTOK*HH;

  // QKV projections (kv = caption)
  tgemm_k<0><<<g768,512,TG_SMEM>>>(NTOK,DD,DD, x,DD,0,       Wqkv,DD,0,         q,DD,0, bqkv,      nullptr,0,0, nullptr,nullptr);
  tgemm_k<0><<<g768,512,TG_SMEM>>>(NTOK,DD,DD, caption,DD,0, Wqkv+DD*DD,DD,0,   k,DD,0, bqkv+DD,   nullptr,0,0, nullptr,nullptr);
  tgemm_k<0><<<g768,512,TG_SMEM>>>(NTOK,DD,DD, caption,DD,0, Wqkv+2*DD*DD,DD,0, v,DD,0, bqkv+2*DD, nullptr,0,0, nullptr,nullptr);

  attn_k<<<dim3(SS/64,NHH,NB),256,ATT_SMEM>>>(q,k,v,o);

  tgemm_k<0><<<g768,512,TG_SMEM>>>(NTOK,DD,DD, o,DD,0, Wo,DD,0, cap,DD,0, bo, nullptr,0,0, nullptr,nullptr);

  // gates + gumbel-softmax
  hilog_k<<<1,128>>>(time_,Whi,bhi,hl);
  mask_k<<<16,256>>>(hl,mk,sk[0][0],sk[0][1]);
  gate_k<<<512,256>>>(cap,     Wcg,bcg,clg);
  gate_k<<<512,256>>>(acoustic,Wag,bag,alg);
  probs_k<<<16,256>>>(clg,pc,sk[1][0],sk[1][1]);
  probs_k<<<16,256>>>(alg,pa,sk[2][0],sk[2][1]);

  // caption expert bank
  tgemm_k<0><<<gE2048,512,TG_SMEM>>>(NTOK,HH,DD, x,DD,0, cw1,DD,(long long)HH*DD, Hg,HH,HgE, nullptr, nullptr,0,0, nullptr,nullptr);
  tgemm_k<1><<<gE2048,512,TG_SMEM>>>(NTOK,HH,DD, x,DD,0, cw3,DD,(long long)HH*DD, Hg,HH,HgE, nullptr, Hg,HH,HgE, nullptr,nullptr);
  tgemm_k<2><<<gE768,512,TG_SMEM>>>(NTOK,DD,HH, Hg,HH,HgE, cw2,HH,(long long)DD*HH, zs,DD,0, nullptr, nullptr,0,0, pc, mk+0);

  // acoustic expert bank
  tgemm_k<0><<<gE2048,512,TG_SMEM>>>(NTOK,HH,DD, x,DD,0, aw1,DD,(long long)HH*DD, Hg,HH,HgE, nullptr, nullptr,0,0, nullptr,nullptr);
  tgemm_k<1><<<gE2048,512,TG_SMEM>>>(NTOK,HH,DD, x,DD,0, aw3,DD,(long long)HH*DD, Hg,HH,HgE, nullptr, Hg,HH,HgE, nullptr,nullptr);
  tgemm_k<2><<<gE768,512,TG_SMEM>>>(NTOK,DD,HH, Hg,HH,HgE, aw2,HH,(long long)DD*HH, zs,DD,0, nullptr, nullptr,0,0, pa, mk+1);

  // fmask expert bank: block-diagonal, K=96 per expert; z written straight to out
  tgemm_k<0><<<gF2048,512,TG_SMEM>>>(NTOK,HH,96, zs,DD,96, fw1,DD,(long long)HH*DD+96, Hg,HH,HgE, nullptr, nullptr,0,0, nullptr,nullptr);
  tgemm_k<1><<<gF2048,512,TG_SMEM>>>(NTOK,HH,96, zs,DD,96, fw3,DD,(long long)HH*DD+96, Hg,HH,HgE, nullptr, Hg,HH,HgE, nullptr,nullptr);
  tgemm_k<0><<<gF96,512,TG_SMEM>>>(NTOK,96,HH, Hg,HH,HgE, fw2,HH,(long long)DD*HH+(long long)96*HH, out,DD,96, nullptr, nullptr,0,0, nullptr,nullptr);

  // load-balance loss -> out[NTOK*DD]
  lossacc_k<<<16,256>>>(pc,pa,mk,ac);
  lossfin_k<<<1,32>>>(ac, out + (long long)NTOK*DD);
}

// round 10
// speedup vs baseline: 3.2418x; 3.2418x over previous
#include <cuda_runtime.h>
#include <cuda_bf16.h>
#include <cstdint>
#include <math.h>

#define NB 2
#define SS 2048
#define DD 768
#define EE 8
#define HH 2048
#define NHH 8
#define NTOK (NB*SS)

// ---------------- scratch ----------------
__device__ float g_q[NTOK*DD];
__device__ float g_k[NTOK*DD];
__device__ float g_v[NTOK*DD];
__device__ float g_o[NTOK*DD];
__device__ float g_cap[NTOK*DD];
__device__ float g_Hg[(size_t)EE*NTOK*HH];
__device__ float g_zsum[NTOK*DD];
__device__ float g_caplog[NTOK*EE];
__device__ float g_aclog[NTOK*EE];
__device__ float g_pc[NTOK*EE];
__device__ float g_pa[NTOK*EE];
__device__ float g_masks[NTOK*2];
__device__ float g_hilog[4];
__device__ float g_accum[17];

// ---------------- threefry2x32 (JAX partitionable) ----------------
__host__ __device__ __forceinline__ uint32_t rotl32(uint32_t v,int r){return (v<<r)|(v>>(32-r));}
__host__ __device__ __forceinline__ void threefry_full(uint32_t k0,uint32_t k1,uint32_t x0,uint32_t x1,
                                                       uint32_t* o0,uint32_t* o1){
  uint32_t ks2 = k0 ^ k1 ^ 0x1BD11BDAu;
  x0 += k0; x1 += k1;
#define TFR(r) x0 += x1; x1 = rotl32(x1,(r)); x1 ^= x0;
  TFR(13) TFR(15) TFR(26) TFR(6)  x0+=k1;  x1+=ks2+1u;
  TFR(17) TFR(29) TFR(16) TFR(24) x0+=ks2; x1+=k0+2u;
  TFR(13) TFR(15) TFR(26) TFR(6)  x0+=k0;  x1+=k1+3u;
  TFR(17) TFR(29) TFR(16) TFR(24) x0+=k1;  x1+=ks2+4u;
  TFR(13) TFR(15) TFR(26) TFR(6)  x0+=ks2; x1+=k0+5u;
#undef TFR
  *o0 = x0; *o1 = x1;
}
__device__ __forceinline__ float gumbel_at(uint32_t k0,uint32_t k1,uint32_t idx){
  uint32_t o0,o1;
  threefry_full(k0,k1,0u,idx,&o0,&o1);
  uint32_t bits = o0 ^ o1;
  float u = __uint_as_float(0x3f800000u | (bits>>9)) - 1.0f;
  u = fmaxf(u, 1.17549435e-38f);
  return -logf(-logf(u));
}

__global__ void zero_k(float* p, long long n){
  long long i=(long long)blockIdx.x*blockDim.x+threadIdx.x, st=(long long)gridDim.x*blockDim.x;
  for(; i<n; i+=st) p[i]=0.f;
}

// ---------------- bf16 mma helpers ----------------
__device__ __forceinline__ void ldsm4(uint32_t* r, uint32_t saddr){
  asm volatile("ldmatrix.sync.aligned.m8n8.x4.shared.b16 {%0,%1,%2,%3}, [%4];"
    : "=r"(r[0]),"=r"(r[1]),"=r"(r[2]),"=r"(r[3]) : "r"(saddr));
}
__device__ __forceinline__ void mma_bf16(float* c, const uint32_t* a, const uint32_t* b2){
  asm volatile("mma.sync.aligned.m16n8k16.row.col.f32.bf16.bf16.f32 "
    "{%0,%1,%2,%3},{%4,%5,%6,%7},{%8,%9},{%0,%1,%2,%3};"
    : "+f"(c[0]),"+f"(c[1]),"+f"(c[2]),"+f"(c[3])
    : "r"(a[0]),"r"(a[1]),"r"(a[2]),"r"(a[3]),"r"(b2[0]),"r"(b2[1]));
}
// pack two fp32 -> bf16x2 (lo -> bits[15:0], hi -> bits[31:16])
__device__ __forceinline__ uint32_t pack_bf16x2(float lo, float hi){
  uint32_t r; asm("cvt.rn.bf16x2.f32 %0, %1, %2;" : "=r"(r) : "f"(hi), "f"(lo)); return r;
}
__device__ __forceinline__ float trunc_bf(float x){
  return __uint_as_float(__float_as_uint(x) & 0xffff0000u);
}

// ------------- bf16 3-split tensor GEMM: C[M,N] = A[M,K] @ W[N,K]^T -------------
// CTA 128x128, 256 threads (8 warps, 2m x 4n), warp tile 64x32, mma m16n8k16 bf16.
// Split x = hi(trunc) + lo(bf16 of residual); acc += Al*Bh + Ah*Bl + Ah*Bh.
// K multiple of 32, M multiple of 128, N-edge guarded (B zero-filled).
// EPI 0: C=acc+bias[col]  EPI 1: C=silu(Dm)*acc  EPI 2: atomicAdd(C, probs*mask*acc)
#define BROW 40   // bf16 row stride (80 bytes): LDSM 16B-aligned + conflict-free
template<int EPI>
__global__ __launch_bounds__(256)
void tcb_k(int M,int N,int K,
           const float* __restrict__ A, long long lda, long long estrA,
           const float* __restrict__ W, long long ldw, long long estrW,
           float* __restrict__ C, long long ldc, long long estrC,
           const float* __restrict__ bias,
           const float* __restrict__ Dm, long long ldd, long long estrD,
           const float* __restrict__ probs, const float* __restrict__ maskp)
{
  const int e = blockIdx.z;
  A += (long long)e*estrA;  W += (long long)e*estrW;  C += (long long)e*estrC;
  if(EPI==1) Dm += (long long)e*estrD;

  __shared__ __align__(16) __nv_bfloat16 sAh[128*BROW];
  __shared__ __align__(16) __nv_bfloat16 sAl[128*BROW];
  __shared__ __align__(16) __nv_bfloat16 sBh[128*BROW];
  __shared__ __align__(16) __nv_bfloat16 sBl[128*BROW];

  const uint32_t aAh = (uint32_t)__cvta_generic_to_shared(sAh);
  const uint32_t aAl = (uint32_t)__cvta_generic_to_shared(sAl);
  const uint32_t aBh = (uint32_t)__cvta_generic_to_shared(sBh);
  const uint32_t aBl = (uint32_t)__cvta_generic_to_shared(sBl);

  const int m0 = blockIdx.y*128, n0 = blockIdx.x*128;
  const int tid = threadIdx.x, w = tid>>5, lane = tid&31;
  const int g = lane>>2, tig = lane&3;
  const int wm = (w>>2)*64, wn = (w&3)*32;

  // ldmatrix per-thread address components
  const int ar0 = (lane&7) + 8*((lane>>3)&1);   // A row-in-tile
  const int ac2 = (lane>>4)*16;                 // A col byte offset (k half)
  const int br0 = (lane&7) + 8*(lane>>4);       // B row-in-tile
  const int bc2 = ((lane>>3)&1)*16;             // B col byte offset

  float acc[4][4][4];
#pragma unroll
  for(int mf=0;mf<4;mf++)
#pragma unroll
    for(int nf=0;nf<4;nf++)
#pragma unroll
      for(int c=0;c<4;c++) acc[mf][nf][c]=0.f;

  const int nch = K>>5;
  float4 pa[4], pw[4];
  // prologue: chunk 0 loads (each thread: 4 float4 of A, 4 of B)
#pragma unroll
  for(int it=0; it<4; it++){
    const int idx = tid + it*256;
    const int row = idx>>3, kg = idx&7;
    pa[it] = *(const float4*)(A + (long long)(m0+row)*lda + kg*4);
    pw[it] = (n0+row < N) ? *(const float4*)(W + (long long)(n0+row)*ldw + kg*4)
                          : make_float4(0.f,0.f,0.f,0.f);
  }

  for(int c=0;c<nch;c++){
    // convert + store to smem
#pragma unroll
    for(int it=0; it<4; it++){
      const int idx = tid + it*256;
      const int row = idx>>3, kg = idx&7;
      // A hi (truncation) / lo (residual)
      {
        uint32_t bx=__float_as_uint(pa[it].x), by=__float_as_uint(pa[it].y),
                 bz=__float_as_uint(pa[it].z), bw=__float_as_uint(pa[it].w);
        uint2 hp;
        hp.x = __byte_perm(bx, by, 0x7632);
        hp.y = __byte_perm(bz, bw, 0x7632);
        uint2 lp;
        lp.x = pack_bf16x2(pa[it].x - trunc_bf(pa[it].x), pa[it].y - trunc_bf(pa[it].y));
        lp.y = pack_bf16x2(pa[it].z - trunc_bf(pa[it].z), pa[it].w - trunc_bf(pa[it].w));
        *(uint2*)(sAh + row*BROW + kg*4) = hp;
        *(uint2*)(sAl + row*BROW + kg*4) = lp;
      }
      {
        uint32_t bx=__float_as_uint(pw[it].x), by=__float_as_uint(pw[it].y),
                 bz=__float_as_uint(pw[it].z), bw=__float_as_uint(pw[it].w);
        uint2 hp;
        hp.x = __byte_perm(bx, by, 0x7632);
        hp.y = __byte_perm(bz, bw, 0x7632);
        uint2 lp;
        lp.x = pack_bf16x2(pw[it].x - trunc_bf(pw[it].x), pw[it].y - trunc_bf(pw[it].y));
        lp.y = pack_bf16x2(pw[it].z - trunc_bf(pw[it].z), pw[it].w - trunc_bf(pw[it].w));
        *(uint2*)(sBh + row*BROW + kg*4) = hp;
        *(uint2*)(sBl + row*BROW + kg*4) = lp;
      }
    }
    __syncthreads();

    // prefetch next chunk (overlaps with mma below)
    if(c+1 < nch){
      const long long kc = (long long)(c+1)*32;
#pragma unroll
      for(int it=0; it<4; it++){
        const int idx = tid + it*256;
        const int row = idx>>3, kg = idx&7;
        pa[it] = *(const float4*)(A + (long long)(m0+row)*lda + kc + kg*4);
        pw[it] = (n0+row < N) ? *(const float4*)(W + (long long)(n0+row)*ldw + kc + kg*4)
                              : make_float4(0.f,0.f,0.f,0.f);
      }
    }

#pragma unroll
    for(int ks=0; ks<2; ks++){
      uint32_t ah[4][4], al[4][4];
#pragma unroll
      for(int mf=0;mf<4;mf++){
        const uint32_t off = (uint32_t)(wm + mf*16 + ar0)*80u + (uint32_t)(ks*32 + ac2);
        ldsm4(ah[mf], aAh + off);
        ldsm4(al[mf], aAl + off);
      }
      uint32_t bh[2][4], bl[2][4];
#pragma unroll
      for(int nfp=0;nfp<2;nfp++){
        const uint32_t off = (uint32_t)(wn + nfp*16 + br0)*80u + (uint32_t)(ks*32 + bc2);
        ldsm4(bh[nfp], aBh + off);
        ldsm4(bl[nfp], aBl + off);
      }
#pragma unroll
      for(int mf=0;mf<4;mf++)
#pragma unroll
        for(int nf=0;nf<4;nf++){
          const uint32_t* bhp = &bh[nf>>1][(nf&1)*2];
          const uint32_t* blp = &bl[nf>>1][(nf&1)*2];
          mma_bf16(acc[mf][nf], al[mf], bhp);
          mma_bf16(acc[mf][nf], ah[mf], blp);
          mma_bf16(acc[mf][nf], ah[mf], bhp);
        }
    }
    __syncthreads();
  }

  // epilogue (register accumulators, direct global writes)
#pragma unroll
  for(int mf=0;mf<4;mf++){
    const int row0 = m0 + wm + mf*16 + g;
    const int row1 = row0 + 8;
    float rs0=0.f, rs1=0.f;
    if(EPI==2){
      rs0 = probs[(long long)row0*8+e]*maskp[(long long)row0*2];
      rs1 = probs[(long long)row1*8+e]*maskp[(long long)row1*2];
    }
#pragma unroll
    for(int nf=0;nf<4;nf++){
      const int col0 = n0 + wn + nf*8 + 2*tig;
#pragma unroll
      for(int cc=0;cc<2;cc++){
        const int col = col0 + cc;
        if(col < N){
          const long long ci0 = (long long)row0*ldc + col;
          const long long ci1 = (long long)row1*ldc + col;
          const float v0 = acc[mf][nf][cc], v1 = acc[mf][nf][2+cc];
          if(EPI==0){
            const float bb = bias ? bias[col] : 0.f;
            C[ci0] = v0 + bb;  C[ci1] = v1 + bb;
          } else if(EPI==1){
            float h0 = Dm[(long long)row0*ldd+col];
            float h1 = Dm[(long long)row1*ldd+col];
            C[ci0] = (h0/(1.f+expf(-h0)))*v0;
            C[ci1] = (h1/(1.f+expf(-h1)))*v1;
          } else {
            atomicAdd(&C[ci0], rs0*v0);
            atomicAdd(&C[ci1], rs1*v1);
          }
        }
      }
    }
  }
}

// ---------------- flash attention (64x64 tiles, online softmax, fp32) ----------------
#define ATT_SMEM ((3*64*97 + 64*65)*4)
__global__ __launch_bounds__(256)
void attn_k(const float* __restrict__ Q, const float* __restrict__ Kg,
            const float* __restrict__ Vg, float* __restrict__ O)
{
  extern __shared__ float sm[];
  float* Qs = sm;
  float* Ks = sm + 64*97;
  float* Vs = sm + 2*64*97;
  float* Ps = sm + 3*64*97;
  const int qt=blockIdx.x, h=blockIdx.y, b=blockIdx.z;
  const int tid=threadIdx.x, ty=tid>>4, tx=tid&15;
  const long long rowbase=(long long)b*SS;

  for(int idx=tid; idx<64*96; idx+=256){
    int r=idx/96, d=idx-r*96;
    Qs[r*97+d] = Q[(rowbase+qt*64+r)*DD + h*96 + d];
  }
  float m[4], l[4], accv[4][6];
#pragma unroll
  for(int i=0;i<4;i++){ m[i]=-1e30f; l[i]=0.f;
#pragma unroll
    for(int d2=0;d2<6;d2++) accv[i][d2]=0.f; }
  const float scale = 1.0f/sqrtf(96.0f);

  for(int t=0;t<SS/64;t++){
    __syncthreads();
    for(int idx=tid; idx<64*96; idx+=256){
      int r=idx/96, d=idx-r*96;
      long long gg=(rowbase+t*64+r)*DD + h*96 + d;
      Ks[r*97+d]=Kg[gg]; Vs[r*97+d]=Vg[gg];
    }
    __syncthreads();

    float s[4][4];
#pragma unroll
    for(int i=0;i<4;i++)
#pragma unroll
      for(int j=0;j<4;j++) s[i][j]=0.f;
    for(int d=0; d<96; d++){
      float a0=Qs[(4*ty+0)*97+d],a1=Qs[(4*ty+1)*97+d],a2=Qs[(4*ty+2)*97+d],a3=Qs[(4*ty+3)*97+d];
      float b0=Ks[(4*tx+0)*97+d],b1=Ks[(4*tx+1)*97+d],b2=Ks[(4*tx+2)*97+d],b3=Ks[(4*tx+3)*97+d];
      s[0][0]+=a0*b0; s[0][1]+=a0*b1; s[0][2]+=a0*b2; s[0][3]+=a0*b3;
      s[1][0]+=a1*b0; s[1][1]+=a1*b1; s[1][2]+=a1*b2; s[1][3]+=a1*b3;
      s[2][0]+=a2*b0; s[2][1]+=a2*b1; s[2][2]+=a2*b2; s[2][3]+=a2*b3;
      s[3][0]+=a3*b0; s[3][1]+=a3*b1; s[3][2]+=a3*b2; s[3][3]+=a3*b3;
    }
#pragma unroll
    for(int i=0;i<4;i++){
      float v0=s[i][0]*scale,v1=s[i][1]*scale,v2=s[i][2]*scale,v3=s[i][3]*scale;
      float mx=fmaxf(fmaxf(v0,v1),fmaxf(v2,v3));
#pragma unroll
      for(int off=8;off>=1;off>>=1) mx=fmaxf(mx,__shfl_xor_sync(0xffffffffu,mx,off));
      float mn=fmaxf(m[i],mx), al=expf(m[i]-mn);
      float p0=expf(v0-mn),p1=expf(v1-mn),p2=expf(v2-mn),p3=expf(v3-mn);
      Ps[(4*ty+i)*65+4*tx+0]=p0; Ps[(4*ty+i)*65+4*tx+1]=p1;
      Ps[(4*ty+i)*65+4*tx+2]=p2; Ps[(4*ty+i)*65+4*tx+3]=p3;
      float ps=p0+p1+p2+p3;
#pragma unroll
      for(int off=8;off>=1;off>>=1) ps+=__shfl_xor_sync(0xffffffffu,ps,off);
      l[i]=l[i]*al+ps; m[i]=mn;
#pragma unroll
      for(int d2=0;d2<6;d2++) accv[i][d2]*=al;
    }
    __syncthreads();
    for(int n=0;n<64;n++){
      float vv[6];
#pragma unroll
      for(int d2=0;d2<6;d2++) vv[d2]=Vs[n*97 + tx*6 + d2];
#pragma unroll
      for(int i=0;i<4;i++){
        float p=Ps[(4*ty+i)*65+n];
#pragma unroll
        for(int d2=0;d2<6;d2++) accv[i][d2]+=p*vv[d2];
      }
    }
  }
#pragma unroll
  for(int i=0;i<4;i++){
    float inv=1.f/l[i];
#pragma unroll
    for(int d2=0;d2<6;d2++)
      O[(rowbase+qt*64+4*ty+i)*DD + h*96 + tx*6+d2] = accv[i][d2]*inv;
  }
}

// ---------------- small kernels ----------------
__global__ void hilog_k(const float* t,const float* Whi,const float* bhi,float* hl){
  int w=threadIdx.x>>5, lane=threadIdx.x&31;
  if(w<4){
    int b=w>>1, j=w&1;
    float s=0.f;
    for(int kk=lane;kk<DD;kk+=32) s += t[b*DD+kk]*Whi[j*DD+kk];
#pragma unroll
    for(int off=16;off>=1;off>>=1) s+=__shfl_xor_sync(0xffffffffu,s,off);
    if(lane==0) hl[b*2+j]=s+bhi[j];
  }
}
__global__ void mask_k(const float* hl,float* mk,uint32_t k0,uint32_t k1){
  int n=blockIdx.x*blockDim.x+threadIdx.x;
  if(n>=NTOK) return;
  int b=n>>11;
  float a0=hl[b*2+0]+gumbel_at(k0,k1,(uint32_t)(2*n));
  float a1=hl[b*2+1]+gumbel_at(k0,k1,(uint32_t)(2*n+1));
  float mx=fmaxf(a0,a1);
  float e0=expf(a0-mx), e1=expf(a1-mx), inv=1.f/(e0+e1);
  mk[2*n+0]=e0*inv; mk[2*n+1]=e1*inv;
}
__global__ __launch_bounds__(256) void gate_k(const float* __restrict__ X,
                                              const float* __restrict__ Wg,
                                              const float* __restrict__ bg,
                                              float* __restrict__ outp){
  int gw=(blockIdx.x*256+threadIdx.x)>>5, lane=threadIdx.x&31;
  if(gw>=NTOK) return;
  const float* xr = X + (long long)gw*DD;
  float acc[8]={0,0,0,0,0,0,0,0};
  for(int kk=lane;kk<DD;kk+=32){
    float xv=xr[kk];
#pragma unroll
    for(int j=0;j<8;j++) acc[j]+=xv*Wg[j*DD+kk];
  }
#pragma unroll
  for(int j=0;j<8;j++){
    float s=acc[j];
#pragma unroll
    for(int off=16;off>=1;off>>=1) s+=__shfl_xor_sync(0xffffffffu,s,off);
    if(lane==0) outp[(long long)gw*8+j]=s+bg[j];
  }
}
__global__ void probs_k(const float* logit,float* pr,uint32_t k0,uint32_t k1){
  int n=blockIdx.x*blockDim.x+threadIdx.x;
  if(n>=NTOK) return;
  float a[8]; float mx=-1e30f;
#pragma unroll
  for(int j=0;j<8;j++){
    a[j]=(logit[n*8+j]+gumbel_at(k0,k1,(uint32_t)(n*8+j)))*0.5f;
    mx=fmaxf(mx,a[j]);
  }
  float sum=0.f;
#pragma unroll
  for(int j=0;j<8;j++){ a[j]=expf(a[j]-mx); sum+=a[j]; }
  float inv=1.f/sum;
#pragma unroll
  for(int j=0;j<8;j++) pr[n*8+j]=a[j]*inv;
}
__global__ void lossacc_k(const float* pc,const float* pa,const float* mk,float* acm){
  __shared__ float sh[17];
  if(threadIdx.x<17) sh[threadIdx.x]=0.f;
  __syncthreads();
  int n=blockIdx.x*blockDim.x+threadIdx.x;
  if(n<NTOK){
    float m0=mk[2*n], m1=mk[2*n+1];
#pragma unroll
    for(int j=0;j<8;j++) atomicAdd(&sh[j],   pc[n*8+j]*m0);
#pragma unroll
    for(int j=0;j<8;j++) atomicAdd(&sh[8+j], pa[n*8+j]*m1);
    atomicAdd(&sh[16], 8.f*(m0+m1));
  }
  __syncthreads();
  if(threadIdx.x<17) atomicAdd(&acm[threadIdx.x], sh[threadIdx.x]);
}
__global__ void lossfin_k(const float* acm,float* outp){
  if(threadIdx.x==0){
    float den=acm[16]+1e-10f, s=0.f;
    for(int j=0;j<16;j++){ float u=acm[j]/den; s += u*logf(u+1e-10f); }
    *outp = s/16.f;
  }
}

// ---------------- launcher ----------------
extern "C" void kernel_launch(void* const* d_in, const int* in_sizes, int n_in,
                              void* d_out, int out_size){
  const float* x        =(const float*)d_in[0];
  const float* time_    =(const float*)d_in[1];
  const float* caption  =(const float*)d_in[2];
  const float* acoustic =(const float*)d_in[3];
  const float* Wqkv     =(const float*)d_in[4];
  const float* bqkv     =(const float*)d_in[5];
  const float* Wo       =(const float*)d_in[6];
  const float* bo       =(const float*)d_in[7];
  const float* Whi      =(const float*)d_in[8];
  const float* bhi      =(const float*)d_in[9];
  const float* Wcg      =(const float*)d_in[10];
  const float* bcg      =(const float*)d_in[11];
  const float* Wag      =(const float*)d_in[12];
  const float* bag      =(const float*)d_in[13];
  const float* cw1      =(const float*)d_in[14];
  const float* cw2      =(const float*)d_in[15];
  const float* cw3      =(const float*)d_in[16];
  const float* aw1      =(const float*)d_in[17];
  const float* aw2      =(const float*)d_in[18];
  const float* aw3      =(const float*)d_in[19];
  const float* fw1      =(const float*)d_in[20];
  const float* fw2      =(const float*)d_in[21];
  const float* fw3      =(const float*)d_in[22];
  float* out=(float*)d_out;

  uint32_t sk[3][2];
  for(uint32_t j=0;j<3;j++) threefry_full(0u,42u,0u,j,&sk[j][0],&sk[j][1]);

  float *q,*k,*v,*o,*cap,*Hg,*zs,*clg,*alg,*pc,*pa,*mk,*hl,*ac;
  cudaGetSymbolAddress((void**)&q,g_q);     cudaGetSymbolAddress((void**)&k,g_k);
  cudaGetSymbolAddress((void**)&v,g_v);     cudaGetSymbolAddress((void**)&o,g_o);
  cudaGetSymbolAddress((void**)&cap,g_cap); cudaGetSymbolAddress((void**)&Hg,g_Hg);
  cudaGetSymbolAddress((void**)&zs,g_zsum); cudaGetSymbolAddress((void**)&clg,g_caplog);
  cudaGetSymbolAddress((void**)&alg,g_aclog);cudaGetSymbolAddress((void**)&pc,g_pc);
  cudaGetSymbolAddress((void**)&pa,g_pa);   cudaGetSymbolAddress((void**)&mk,g_masks);
  cudaGetSymbolAddress((void**)&hl,g_hilog);cudaGetSymbolAddress((void**)&ac,g_accum);

  cudaFuncSetAttribute(attn_k, cudaFuncAttributeMaxDynamicSharedMemorySize, ATT_SMEM);

  zero_k<<<256,256>>>(zs,(long long)NTOK*DD);
  zero_k<<<1,32>>>(ac,17);

  dim3 g768(6,32,1), gE2048(16,32,8), gE768(6,32,8), gF2048(16,32,8), gF96(1,32,8);
  const long long HgE=(long long)NTOK*HH;

  // QKV projections (kv = caption)
  tcb_k<0><<<g768,256>>>(NTOK,DD,DD, x,DD,0,       Wqkv,DD,0,         q,DD,0, bqkv,      nullptr,0,0, nullptr,nullptr);
  tcb_k<0><<<g768,256>>>(NTOK,DD,DD, caption,DD,0, Wqkv+DD*DD,DD,0,   k,DD,0, bqkv+DD,   nullptr,0,0, nullptr,nullptr);
  tcb_k<0><<<g768,256>>>(NTOK,DD,DD, caption,DD,0, Wqkv+2*DD*DD,DD,0, v,DD,0, bqkv+2*DD, nullptr,0,0, nullptr,nullptr);

  attn_k<<<dim3(SS/64,NHH,NB),256,ATT_SMEM>>>(q,k,v,o);

  tcb_k<0><<<g768,256>>>(NTOK,DD,DD, o,DD,0, Wo,DD,0, cap,DD,0, bo, nullptr,0,0, nullptr,nullptr);

  // gates + gumbel-softmax
  hilog_k<<<1,128>>>(time_,Whi,bhi,hl);
  mask_k<<<16,256>>>(hl,mk,sk[0][0],sk[0][1]);
  gate_k<<<512,256>>>(cap,     Wcg,bcg,clg);
  gate_k<<<512,256>>>(acoustic,Wag,bag,alg);
  probs_k<<<16,256>>>(clg,pc,sk[1][0],sk[1][1]);
  probs_k<<<16,256>>>(alg,pa,sk[2][0],sk[2][1]);

  // caption expert bank
  tcb_k<0><<<gE2048,256>>>(NTOK,HH,DD, x,DD,0, cw1,DD,(long long)HH*DD, Hg,HH,HgE, nullptr, nullptr,0,0, nullptr,nullptr);
  tcb_k<1><<<gE2048,256>>>(NTOK,HH,DD, x,DD,0, cw3,DD,(long long)HH*DD, Hg,HH,HgE, nullptr, Hg,HH,HgE, nullptr,nullptr);
  tcb_k<2><<<gE768,256>>>(NTOK,DD,HH, Hg,HH,HgE, cw2,HH,(long long)DD*HH, zs,DD,0, nullptr, nullptr,0,0, pc, mk+0);

  // acoustic expert bank
  tcb_k<0><<<gE2048,256>>>(NTOK,HH,DD, x,DD,0, aw1,DD,(long long)HH*DD, Hg,HH,HgE, nullptr, nullptr,0,0, nullptr,nullptr);
  tcb_k<1><<<gE2048,256>>>(NTOK,HH,DD, x,DD,0, aw3,DD,(long long)HH*DD, Hg,HH,HgE, nullptr, Hg,HH,HgE, nullptr,nullptr);
  tcb_k<2><<<gE768,256>>>(NTOK,DD,HH, Hg,HH,HgE, aw2,HH,(long long)DD*HH, zs,DD,0, nullptr, nullptr,0,0, pa, mk+1);

  // fmask expert bank: block-diagonal, K=96 per expert; z written straight to out
  tcb_k<0><<<gF2048,256>>>(NTOK,HH,96, zs,DD,96, fw1,DD,(long long)HH*DD+96, Hg,HH,HgE, nullptr, nullptr,0,0, nullptr,nullptr);
  tcb_k<1><<<gF2048,256>>>(NTOK,HH,96, zs,DD,96, fw3,DD,(long long)HH*DD+96, Hg,HH,HgE, nullptr, Hg,HH,HgE, nullptr,nullptr);
  tcb_k<0><<<gF96,256>>>(NTOK,96,HH, Hg,HH,HgE, fw2,HH,(long long)DD*HH+(long long)96*HH, out,DD,96, nullptr, nullptr,0,0, nullptr,nullptr);

  // load-balance loss -> out[NTOK*DD]
  lossacc_k<<<16,256>>>(pc,pa,mk,ac);
  lossfin_k<<<1,32>>>(ac, out + (long long)NTOK*DD);
}